// round 6
// baseline (speedup 1.0000x reference)
#include <cuda_runtime.h>
#include <cstdint>

// Conv2d 3x3 s1 p1 NCHW fp32: N=32,C=128,H=W=56,OC=256.
// Implicit GEMM, mma.sync.m16n8k8.tf32, K reordered as k' = tap*128 + c.
// R6: 1 CTA/SM (regs ~150), explicit fragment double-buffering across k-steps,
// 4-buffer cp.async ring with wait_group 2.

#define N_IMG   32
#define C_IN    128
#define H_DIM   56
#define W_DIM   56
#define OC_DIM  256
#define HW      3136
#define K_TOTAL 1152
#define M_TOTAL 100352

#define BM 128
#define BN 128
#define BK 32
#define THREADS 256
#define NSTAGES 36                      // K_TOTAL / BK
#define NBUF 4

#define STAGE_BYTES 32768               // A 16KB + B 16KB (fragment order)
#define SMEM_TOTAL  (NBUF * STAGE_BYTES) // 128KB

__device__ __align__(16) float    g_in_t[N_IMG * C_IN * HW];   // tf32 input copy
__device__ __align__(16) uint32_t g_w_t[OC_DIM * K_TOTAL];     // tf32 frag weights

__device__ __forceinline__ uint32_t smem_u32(const void* p) {
    uint32_t a;
    asm("{ .reg .u64 t; cvta.to.shared.u64 t, %1; cvt.u32.u64 %0, t; }" : "=r"(a) : "l"(p));
    return a;
}
__device__ __forceinline__ uint32_t f2tf32(float f) {
    uint32_t u;
    asm("cvt.rna.tf32.f32 %0, %1;" : "=r"(u) : "f"(f));
    return u;
}
__device__ __forceinline__ void cp4_zfill(uint32_t dst, const void* src, uint32_t sz) {
    asm volatile("cp.async.ca.shared.global [%0], [%1], 4, %2;"
                 :: "r"(dst), "l"(src), "r"(sz) : "memory");
}
__device__ __forceinline__ void cp16(uint32_t dst, const void* src) {
    asm volatile("cp.async.cg.shared.global [%0], [%1], 16;"
                 :: "r"(dst), "l"(src) : "memory");
}
__device__ __forceinline__ void lds128(uint32_t* r, uint32_t addr) {
    asm volatile("ld.shared.v4.u32 {%0,%1,%2,%3}, [%4];"
                 : "=r"(r[0]), "=r"(r[1]), "=r"(r[2]), "=r"(r[3]) : "r"(addr));
}
__device__ __forceinline__ void mma_tf32(float* c,
                                         const uint32_t* a, uint32_t b0, uint32_t b1) {
    asm volatile(
        "mma.sync.aligned.m16n8k8.row.col.f32.tf32.tf32.f32 "
        "{%0,%1,%2,%3}, {%4,%5,%6,%7}, {%8,%9}, {%0,%1,%2,%3};"
        : "+f"(c[0]), "+f"(c[1]), "+f"(c[2]), "+f"(c[3])
        : "r"(a[0]), "r"(a[1]), "r"(a[2]), "r"(a[3]), "r"(b0), "r"(b1));
}

// ---- prep: input -> tf32 bits, same layout ----
__global__ void prep_in_kernel(const float* __restrict__ in) {
    const int i = blockIdx.x * blockDim.x + threadIdx.x;   // float4 index
    float4 v = ((const float4*)in)[i];
    float4 o;
    o.x = __uint_as_float(f2tf32(v.x));
    o.y = __uint_as_float(f2tf32(v.y));
    o.z = __uint_as_float(f2tf32(v.z));
    o.w = __uint_as_float(f2tf32(v.w));
    ((float4*)g_in_t)[i] = o;
}

// ---- prep: weights -> tf32, fragment order keyed by k' = rs*128 + c ----
__global__ void prep_w_kernel(const float* __restrict__ w) {
    const int idx = blockIdx.x * blockDim.x + threadIdx.x;  // oc*1152 + c*9 + rs
    const int oc = idx / K_TOTAL;
    const int kf = idx - oc * K_TOTAL;
    const int c  = kf / 9;
    const int rs = kf - c * 9;
    const int kp = rs * 128 + c;             // reordered K
    const int s   = kp >> 5;
    const int kl  = kp & 31;
    const int ks  = kl >> 3;
    const int tig = kl & 3;
    const int kh  = (kl >> 2) & 1;
    const int nh  = oc >> 7;
    const int ocl = oc & 127;
    const int tp  = ocl >> 4;
    const int tpo = (ocl >> 3) & 1;
    const int grp = ocl & 7;
    const int word = ((s * 2 + nh) * 4 + ks) * 1024
                   + tp * 128 + grp * 16 + tig * 4 + tpo * 2 + kh;
    g_w_t[word] = f2tf32(w[idx]);
}

__global__ void __launch_bounds__(THREADS)
conv2d_mma_kernel(const float* __restrict__ bias, float* __restrict__ out)
{
    extern __shared__ char smem_raw[];
    const uint32_t sbase = smem_u32(smem_raw);

    const int tid     = threadIdx.x;
    const int lane    = tid & 31;
    const int wid     = tid >> 5;
    const int m_base  = blockIdx.x * BM;
    const int nhalf   = blockIdx.y;            // oc half (0 / 1)
    const int oc_base = nhalf * BN;

    // ---- A gather mapping ----
    const int a_m    = tid & 127;
    const int a_kq   = (tid >> 7) * 16;        // k_local base: 0 or 16
    const int tile_m = a_m >> 4;
    const int grp_w  = a_m & 7;
    const int half_w = (a_m >> 3) & 1;
    const int m_g    = m_base + a_m;
    const int n_img  = m_g / HW;
    const int hw     = m_g - n_img * HW;
    const int h      = hw / W_DIM;
    const int w      = hw - h * W_DIM;
    const float* in_t_n = g_in_t + (size_t)n_img * (C_IN * HW) + hw;

    const uint32_t a_dst0 = (uint32_t)((a_kq >> 3) * 1024 + tile_m * 128
                                       + grp_w * 4 + half_w);

    // ---- loader state (stage lt, tap = lt>>2) ----
    int lt = 0, lr = 0, lsq = 0;
    auto load_next = [&]() {
        const uint32_t abase = sbase + (lt & (NBUF - 1)) * STAGE_BYTES;
        const uint32_t bbase = abase + 16384;
        const bool ok = ((unsigned)(h + lr - 1) < (unsigned)H_DIM) &&
                        ((unsigned)(w + lsq - 1) < (unsigned)W_DIM);
        const uint32_t sz = ok ? 4u : 0u;
        const float* p = in_t_n + (lr - 1) * W_DIM + (lsq - 1)
                       + (size_t)((lt & 3) * 32 + a_kq) * HW;
        const uint32_t adst = abase + a_dst0 * 4;
        #pragma unroll
        for (int j = 0; j < 16; j++) {
            const uint32_t dj = (uint32_t)((j >> 3) * 1024 + (j & 3) * 32
                               + ((j >> 2) & 1) * 2) * 4;
            cp4_zfill(adst + dj, p + (size_t)j * HW, sz);
        }
        const uint32_t* wsrc = g_w_t + (size_t)(lt * 2 + nhalf) * 4096;
        #pragma unroll
        for (int j = 0; j < 4; j++) {
            const int cchunk = tid + 256 * j;
            cp16(bbase + cchunk * 16, wsrc + cchunk * 4);
        }
        asm volatile("cp.async.commit_group;" ::: "memory");
        lt++;
        if ((lt & 3) == 0) { lsq++; if (lsq == 3) { lsq = 0; lr++; } }
    };

    // ---- compute mapping: 4(M) x 2(N) warps, warp tile 32x64 ----
    const int wm  = wid & 3;
    const int wn  = wid >> 2;
    const int grp = lane >> 2;
    const int tig = lane & 3;
    const uint32_t a_roff = (uint32_t)((tig * 8 + grp) * 16);   // bytes
    const uint32_t b_roff = (uint32_t)(grp * 64 + tig * 16);    // bytes

    float acc[2][8][4];
    #pragma unroll
    for (int mi = 0; mi < 2; mi++)
        #pragma unroll
        for (int ni = 0; ni < 8; ni++)
            #pragma unroll
            for (int q = 0; q < 4; q++) acc[mi][ni][q] = 0.0f;

    load_next();            // stage 0 -> buf 0
    load_next();            // stage 1 -> buf 1
    load_next();            // stage 2 -> buf 2

    for (int s = 0; s < NSTAGES; s++) {
        asm volatile("cp.async.wait_group 2;" ::: "memory");
        __syncthreads();
        // buf (s+3)%4 == (s-1)%4 was consumed at stage s-1; refill now
        if (s + 3 < NSTAGES) load_next();
        else asm volatile("cp.async.commit_group;" ::: "memory");

        const uint32_t Ab = sbase + (s & (NBUF - 1)) * STAGE_BYTES;
        const uint32_t Bb = Ab + 16384;

        // ---- k-step pipelined fragments: LDS(ks+1) before MMA(ks) ----
        uint32_t a[2][2][4];    // [pipe][mi][regs]
        uint32_t b[2][4][4];    // [pipe][t][regs]
        #pragma unroll
        for (int mi = 0; mi < 2; mi++)
            lds128(a[0][mi], Ab + (uint32_t)((wm * 2 + mi) * 512) + a_roff);
        #pragma unroll
        for (int t = 0; t < 4; t++)
            lds128(b[0][t], Bb + (uint32_t)((wn * 4 + t) * 512) + b_roff);

        #pragma unroll
        for (int ks = 0; ks < 4; ks++) {
            const int cur = ks & 1, nxt = cur ^ 1;
            if (ks < 3) {
                #pragma unroll
                for (int mi = 0; mi < 2; mi++)
                    lds128(a[nxt][mi],
                           Ab + (uint32_t)(((ks + 1) * 8 + wm * 2 + mi) * 512) + a_roff);
                #pragma unroll
                for (int t = 0; t < 4; t++)
                    lds128(b[nxt][t],
                           Bb + (uint32_t)(((ks + 1) * 8 + wn * 4 + t) * 512) + b_roff);
            }
            #pragma unroll
            for (int t = 0; t < 4; t++)
                #pragma unroll
                for (int tpo = 0; tpo < 2; tpo++) {
                    const int ni = t * 2 + tpo;
                    #pragma unroll
                    for (int mi = 0; mi < 2; mi++)
                        mma_tf32(acc[mi][ni], a[cur][mi],
                                 b[cur][t][tpo * 2], b[cur][t][tpo * 2 + 1]);
                }
        }
    }

    // ---- epilogue: +bias (fp32), scatter to NCHW ----
    #pragma unroll
    for (int mi = 0; mi < 2; mi++) {
        const int row0 = m_base + wm * 32 + mi * 16 + grp;
        #pragma unroll
        for (int hf = 0; hf < 2; hf++) {
            const int m   = row0 + 8 * hf;
            const int nn  = m / HW;
            const int phw = m - nn * HW;
            float* op = out + (size_t)nn * OC_DIM * HW + phw;
            #pragma unroll
            for (int ni = 0; ni < 8; ni++) {
                const int oc = oc_base + wn * 64 + ni * 8 + 2 * tig;
                const float b0 = __ldg(bias + oc);
                const float b1 = __ldg(bias + oc + 1);
                op[(size_t)oc * HW]       = acc[mi][ni][2 * hf + 0] + b0;
                op[(size_t)(oc + 1) * HW] = acc[mi][ni][2 * hf + 1] + b1;
            }
        }
    }
}

extern "C" void kernel_launch(void* const* d_in, const int* in_sizes, int n_in,
                              void* d_out, int out_size)
{
    const float* in   = (const float*)d_in[0];
    const float* wgt  = (const float*)d_in[1];
    const float* bias = (const float*)d_in[2];
    float* out        = (float*)d_out;

    prep_in_kernel<<<(N_IMG * C_IN * HW / 4) / 256, 256>>>(in);
    prep_w_kernel<<<(OC_DIM * K_TOTAL) / 256, 256>>>(wgt);

    cudaFuncSetAttribute(conv2d_mma_kernel,
                         cudaFuncAttributeMaxDynamicSharedMemorySize, SMEM_TOTAL);
    dim3 grid(M_TOTAL / BM, OC_DIM / BN, 1);   // 784 x 2
    conv2d_mma_kernel<<<grid, THREADS, SMEM_TOTAL>>>(bias, out);
}

// round 7
// speedup vs baseline: 1.5316x; 1.5316x over previous
#include <cuda_runtime.h>
#include <cstdint>

// Conv2d 3x3 s1 p1 NCHW fp32: N=32,C=128,H=W=56,OC=256.
// Implicit GEMM mma.sync.m16n8k8.tf32. K order: k' = cblk*288 + tap*32 + c.
// R7: raw A tile (128 pix + halo = 248) loaded ONCE per 32-channel block
// (9 stages) via cp16; per-tap shifted scalar LDS + validity selects replace
// the per-stage im2col regather.

#define N_IMG   32
#define C_IN    128
#define H_DIM   56
#define W_DIM   56
#define OC_DIM  256
#define HW      3136
#define K_TOTAL 1152
#define M_TOTAL 100352
#define CHW     (C_IN * HW)

#define BM 128
#define BN 128
#define THREADS 256
#define NSTAGES 36                       // 4 cblk * 9 taps

#define ASTRIDE 248                      // pixels per channel row (m block + halo)
#define ABUF_BYTES (32 * ASTRIDE * 4)    // 31744
#define B_STAGE_BYTES 16384
#define A_OFF(i) ((i) * ABUF_BYTES)
#define B_OFF(j) (2 * ABUF_BYTES + (j) * B_STAGE_BYTES)
#define SMEM_TOTAL (2 * ABUF_BYTES + 3 * B_STAGE_BYTES)   // 112640

__device__ __align__(16) float    g_in_t[N_IMG * CHW];     // tf32 input copy
__device__ __align__(16) uint32_t g_w_t[OC_DIM * K_TOTAL]; // tf32 frag weights

__device__ __forceinline__ uint32_t smem_u32(const void* p) {
    uint32_t a;
    asm("{ .reg .u64 t; cvta.to.shared.u64 t, %1; cvt.u32.u64 %0, t; }" : "=r"(a) : "l"(p));
    return a;
}
__device__ __forceinline__ uint32_t f2tf32(float f) {
    uint32_t u;
    asm("cvt.rna.tf32.f32 %0, %1;" : "=r"(u) : "f"(f));
    return u;
}
__device__ __forceinline__ void cp4_zfill(uint32_t dst, const void* src, uint32_t sz) {
    asm volatile("cp.async.ca.shared.global [%0], [%1], 4, %2;"
                 :: "r"(dst), "l"(src), "r"(sz) : "memory");
}
__device__ __forceinline__ void cp16(uint32_t dst, const void* src) {
    asm volatile("cp.async.cg.shared.global [%0], [%1], 16;"
                 :: "r"(dst), "l"(src) : "memory");
}
__device__ __forceinline__ uint32_t lds32(uint32_t addr) {
    uint32_t v;
    asm volatile("ld.shared.u32 %0, [%1];" : "=r"(v) : "r"(addr));
    return v;
}
__device__ __forceinline__ void lds128(uint32_t* r, uint32_t addr) {
    asm volatile("ld.shared.v4.u32 {%0,%1,%2,%3}, [%4];"
                 : "=r"(r[0]), "=r"(r[1]), "=r"(r[2]), "=r"(r[3]) : "r"(addr));
}
__device__ __forceinline__ void mma_tf32(float* c,
                                         const uint32_t* a, uint32_t b0, uint32_t b1) {
    asm volatile(
        "mma.sync.aligned.m16n8k8.row.col.f32.tf32.tf32.f32 "
        "{%0,%1,%2,%3}, {%4,%5,%6,%7}, {%8,%9}, {%0,%1,%2,%3};"
        : "+f"(c[0]), "+f"(c[1]), "+f"(c[2]), "+f"(c[3])
        : "r"(a[0]), "r"(a[1]), "r"(a[2]), "r"(a[3]), "r"(b0), "r"(b1));
}

// ---- prep: input -> tf32 bits, same layout ----
__global__ void prep_in_kernel(const float* __restrict__ in) {
    const int i = blockIdx.x * blockDim.x + threadIdx.x;
    float4 v = ((const float4*)in)[i];
    float4 o;
    o.x = __uint_as_float(f2tf32(v.x));
    o.y = __uint_as_float(f2tf32(v.y));
    o.z = __uint_as_float(f2tf32(v.z));
    o.w = __uint_as_float(f2tf32(v.w));
    ((float4*)g_in_t)[i] = o;
}

// ---- prep: weights -> tf32, fragment order keyed by k' = cblk*288+tap*32+c ----
__global__ void prep_w_kernel(const float* __restrict__ w) {
    const int idx = blockIdx.x * blockDim.x + threadIdx.x;  // oc*1152 + c_full*9 + rs
    const int oc = idx / K_TOTAL;
    const int kf = idx - oc * K_TOTAL;
    const int c_full = kf / 9;
    const int rs = kf - c_full * 9;
    const int cblk = c_full >> 5;
    const int cl   = c_full & 31;
    const int s    = cblk * 9 + rs;          // stage
    const int kl   = cl;                     // k within stage
    const int ks   = kl >> 3;
    const int tig  = kl & 3;
    const int kh   = (kl >> 2) & 1;
    const int nh   = oc >> 7;
    const int ocl  = oc & 127;
    const int tp   = ocl >> 4;
    const int tpo  = (ocl >> 3) & 1;
    const int grp  = ocl & 7;
    const int word = ((s * 2 + nh) * 4 + ks) * 1024
                   + tp * 128 + grp * 16 + tig * 4 + tpo * 2 + kh;
    g_w_t[word] = f2tf32(w[idx]);
}

__global__ void __launch_bounds__(THREADS, 2)
conv2d_mma_kernel(const float* __restrict__ bias, float* __restrict__ out)
{
    extern __shared__ char smem_raw[];
    const uint32_t sbase = smem_u32(smem_raw);

    const int tid     = threadIdx.x;
    const int lane    = tid & 31;
    const int wid     = tid >> 5;
    const int m_base  = blockIdx.x * BM;
    const int nhalf   = blockIdx.y;
    const int oc_base = nhalf * BN;

    // ---- raw A loader mapping: thread -> (channel c_loc, pixel group) ----
    const int c_loc = tid >> 3;             // 0..31
    const int g0l   = (tid & 7) * 4;        // 0,4,..,28
    const uint32_t adst_base = (uint32_t)(c_loc * ASTRIDE * 4 + g0l * 4);

    auto load_A = [&](int cblk) {
        const uint32_t dbase = sbase + A_OFF(cblk & 1) + adst_base;
        const float* ch_base = g_in_t + (size_t)(cblk * 32 + c_loc) * HW;
        #pragma unroll
        for (int j = 0; j < 8; j++) {
            const int gl = g0l + 32 * j;
            if (gl >= ASTRIDE) break;
            const int g0 = m_base - 60 + gl;
            const uint32_t dst = dbase + (uint32_t)(32 * j * 4);
            bool fast = (g0 >= 0) && (g0 + 3 < M_TOTAL);
            int n = 0, rem = 0;
            if (fast) {
                n = g0 / HW; rem = g0 - n * HW;
                fast = (rem <= HW - 4);
            }
            if (fast) {
                cp16(dst, ch_base + (size_t)n * CHW + rem);
            } else {
                #pragma unroll
                for (int e = 0; e < 4; e++) {
                    const int g = g0 + e;
                    const float* src = g_in_t;
                    uint32_t sz = 0;
                    if (g >= 0 && g < M_TOTAL) {
                        const int nn = g / HW;
                        src = ch_base + (size_t)nn * CHW + (g - nn * HW);
                        sz = 4;
                    }
                    cp4_zfill(dst + 4 * e, src, sz);
                }
            }
        }
    };

    auto load_B = [&](int s) {
        const uint32_t bbase = sbase + B_OFF(s % 3);
        const uint32_t* wsrc = g_w_t + (size_t)(s * 2 + nhalf) * 4096;
        #pragma unroll
        for (int j = 0; j < 4; j++) {
            const int cchunk = tid + 256 * j;
            cp16(bbase + cchunk * 16, wsrc + cchunk * 4);
        }
    };

    // ---- compute mapping: 4(M) x 2(N) warps, warp tile 32x64 ----
    const int wm  = wid & 3;
    const int wn  = wid >> 2;
    const int grp = lane >> 2;
    const int tig = lane & 3;
    const uint32_t b_roff = (uint32_t)(grp * 64 + tig * 16);

    // per-thread m rows: wm*32 + grp + 8*i, i=0..3
    const int mrow0 = wm * 32 + grp;
    int hh[4], ww[4];
    #pragma unroll
    for (int i = 0; i < 4; i++) {
        const int m  = m_base + mrow0 + 8 * i;
        const int nn = m / HW;
        const int hw = m - nn * HW;
        hh[i] = hw / W_DIM;
        ww[i] = hw - hh[i] * W_DIM;
    }

    float acc[2][8][4];
    #pragma unroll
    for (int mi = 0; mi < 2; mi++)
        #pragma unroll
        for (int ni = 0; ni < 8; ni++)
            #pragma unroll
            for (int q = 0; q < 4; q++) acc[mi][ni][q] = 0.0f;

    // ---- prologue: A0+B0 | A1+B1 | B2 (3 commit groups) ----
    load_A(0); load_B(0);
    asm volatile("cp.async.commit_group;" ::: "memory");
    load_A(1); load_B(1);
    asm volatile("cp.async.commit_group;" ::: "memory");
    load_B(2);
    asm volatile("cp.async.commit_group;" ::: "memory");

    int tap = 0, cblk = 0, dh = -1, dw = -1;
    for (int s = 0; s < NSTAGES; s++) {
        asm volatile("cp.async.wait_group 2;" ::: "memory");
        __syncthreads();

        const uint32_t Ab = sbase + A_OFF(cblk & 1);
        const uint32_t Bb = sbase + B_OFF(s % 3);

        // per-stage A addresses + validity (tap-dependent)
        const int offp = dh * W_DIM + dw + 60;
        uint32_t abase_i[4];
        bool val[4];
        #pragma unroll
        for (int i = 0; i < 4; i++) {
            abase_i[i] = Ab + (uint32_t)((mrow0 + 8 * i + offp) * 4 + tig * (ASTRIDE * 4));
            val[i] = ((unsigned)(hh[i] + dh) < (unsigned)H_DIM) &&
                     ((unsigned)(ww[i] + dw) < (unsigned)W_DIM);
        }

        #pragma unroll
        for (int ks = 0; ks < 4; ks++) {
            const uint32_t ksoff = (uint32_t)(ks * 8 * ASTRIDE * 4);
            uint32_t a[2][4];
            #pragma unroll
            for (int mi = 0; mi < 2; mi++) {
                const int i0 = 2 * mi, i1 = 2 * mi + 1;
                uint32_t v0 = lds32(abase_i[i0] + ksoff);
                uint32_t v1 = lds32(abase_i[i1] + ksoff);
                uint32_t v2 = lds32(abase_i[i0] + ksoff + 4 * ASTRIDE * 4);
                uint32_t v3 = lds32(abase_i[i1] + ksoff + 4 * ASTRIDE * 4);
                a[mi][0] = val[i0] ? v0 : 0u;
                a[mi][1] = val[i1] ? v1 : 0u;
                a[mi][2] = val[i0] ? v2 : 0u;
                a[mi][3] = val[i1] ? v3 : 0u;
            }
            uint32_t bb[4][4];
            #pragma unroll
            for (int t = 0; t < 4; t++)
                lds128(bb[t], Bb + (uint32_t)((ks * 8 + wn * 4 + t) * 512) + b_roff);
            #pragma unroll
            for (int t = 0; t < 4; t++)
                #pragma unroll
                for (int tpo = 0; tpo < 2; tpo++) {
                    const int ni = t * 2 + tpo;
                    #pragma unroll
                    for (int mi = 0; mi < 2; mi++)
                        mma_tf32(acc[mi][ni], a[mi],
                                 bb[t][tpo * 2], bb[t][tpo * 2 + 1]);
                }
        }
        __syncthreads();

        if (s + 3 < NSTAGES) load_B(s + 3);
        if (tap == 0 && cblk < 3) load_A(cblk + 1);
        asm volatile("cp.async.commit_group;" ::: "memory");

        if (++tap == 9) { tap = 0; cblk++; dh = -1; dw = -1; }
        else { if (++dw == 2) { dw = -1; dh++; } }
    }

    // ---- epilogue: +bias, scatter to NCHW ----
    #pragma unroll
    for (int mi = 0; mi < 2; mi++) {
        #pragma unroll
        for (int hf = 0; hf < 2; hf++) {
            const int m   = m_base + mrow0 + mi * 16 + 8 * hf;
            const int nn  = m / HW;
            const int phw = m - nn * HW;
            float* op = out + (size_t)nn * OC_DIM * HW + phw;
            #pragma unroll
            for (int ni = 0; ni < 8; ni++) {
                const int oc = oc_base + wn * 64 + ni * 8 + 2 * tig;
                const float b0 = __ldg(bias + oc);
                const float b1 = __ldg(bias + oc + 1);
                op[(size_t)oc * HW]       = acc[mi][ni][2 * hf + 0] + b0;
                op[(size_t)(oc + 1) * HW] = acc[mi][ni][2 * hf + 1] + b1;
            }
        }
    }
}

extern "C" void kernel_launch(void* const* d_in, const int* in_sizes, int n_in,
                              void* d_out, int out_size)
{
    const float* in   = (const float*)d_in[0];
    const float* wgt  = (const float*)d_in[1];
    const float* bias = (const float*)d_in[2];
    float* out        = (float*)d_out;

    prep_in_kernel<<<(N_IMG * CHW / 4) / 256, 256>>>(in);
    prep_w_kernel<<<(OC_DIM * K_TOTAL) / 256, 256>>>(wgt);

    cudaFuncSetAttribute(conv2d_mma_kernel,
                         cudaFuncAttributeMaxDynamicSharedMemorySize, SMEM_TOTAL);
    dim3 grid(M_TOTAL / BM, OC_DIM / BN, 1);   // 784 x 2
    conv2d_mma_kernel<<<grid, THREADS, SMEM_TOTAL>>>(bias, out);
}

// round 8
// speedup vs baseline: 2.1477x; 1.4022x over previous
#include <cuda_runtime.h>
#include <cuda_fp16.h>
#include <cstdint>

// Conv2d 3x3 s1 p1 NCHW fp32: N=32,C=128,H=W=56,OC=256.
// Implicit GEMM mma.sync.m16n8k16 FP16 (fp32 accum). K' = cblk*288 + tap*32 + c.
// R8: fp16 operands (same 11-bit significand as tf32), warp tile 32x32,
// BN=64, 4 CTAs/SM (no register spills), raw A tile as fp16x2 channel pairs.

#define N_IMG   32
#define C_IN    128
#define H_DIM   56
#define W_DIM   56
#define OC_DIM  256
#define HW      3136
#define K_TOTAL 1152
#define M_TOTAL 100352

#define BM 128
#define BN 64
#define THREADS 256
#define NSTAGES 36                       // 4 cblk * 9 taps

#define ASTRIDE 248                      // u32 (=fp16x2 channel-pair) per row
#define ABUF_BYTES (16 * ASTRIDE * 4)    // 15872 (16 ch-pairs x 248 pix)
#define B_STAGE_BYTES 4096               // 64 oc x 32 k x 2B
#define A_OFF(i) ((i) * ABUF_BYTES)
#define B_OFF(j) (2 * ABUF_BYTES + (j) * B_STAGE_BYTES)
#define SMEM_TOTAL (2 * ABUF_BYTES + 3 * B_STAGE_BYTES)   // 44032

__device__ __align__(16) uint32_t g_in_h[N_IMG * 64 * HW];   // [n][cp][hw] fp16x2
__device__ __align__(16) uint32_t g_w_h[OC_DIM * K_TOTAL / 2]; // frag-order fp16x2

__device__ __forceinline__ uint32_t smem_u32(const void* p) {
    uint32_t a;
    asm("{ .reg .u64 t; cvta.to.shared.u64 t, %1; cvt.u32.u64 %0, t; }" : "=r"(a) : "l"(p));
    return a;
}
__device__ __forceinline__ uint32_t pack_h2(float lo, float hi) {
    __half2 h = __halves2half2(__float2half_rn(lo), __float2half_rn(hi));
    return *reinterpret_cast<uint32_t*>(&h);
}
__device__ __forceinline__ void cp4_zfill(uint32_t dst, const void* src, uint32_t sz) {
    asm volatile("cp.async.ca.shared.global [%0], [%1], 4, %2;"
                 :: "r"(dst), "l"(src), "r"(sz) : "memory");
}
__device__ __forceinline__ void cp16(uint32_t dst, const void* src) {
    asm volatile("cp.async.cg.shared.global [%0], [%1], 16;"
                 :: "r"(dst), "l"(src) : "memory");
}
__device__ __forceinline__ uint32_t lds32(uint32_t addr) {
    uint32_t v;
    asm volatile("ld.shared.u32 %0, [%1];" : "=r"(v) : "r"(addr));
    return v;
}
__device__ __forceinline__ void lds128(uint32_t* r, uint32_t addr) {
    asm volatile("ld.shared.v4.u32 {%0,%1,%2,%3}, [%4];"
                 : "=r"(r[0]), "=r"(r[1]), "=r"(r[2]), "=r"(r[3]) : "r"(addr));
}
__device__ __forceinline__ void mma_f16(float* c, const uint32_t* a,
                                        uint32_t b0, uint32_t b1) {
    asm volatile(
        "mma.sync.aligned.m16n8k16.row.col.f32.f16.f16.f32 "
        "{%0,%1,%2,%3}, {%4,%5,%6,%7}, {%8,%9}, {%0,%1,%2,%3};"
        : "+f"(c[0]), "+f"(c[1]), "+f"(c[2]), "+f"(c[3])
        : "r"(a[0]), "r"(a[1]), "r"(a[2]), "r"(a[3]), "r"(b0), "r"(b1));
}

// ---- prep: input -> fp16x2 channel-pair layout: [n][cp=c/2][hw] ----
__global__ void prep_in_kernel(const float* __restrict__ in) {
    const int idx = blockIdx.x * blockDim.x + threadIdx.x;  // [0, 32*64*784)
    const int ncp = idx / 784;
    const int q   = idx - ncp * 784;
    const int n   = ncp >> 6;
    const int cp  = ncp & 63;
    const float4 v0 = ((const float4*)in)[(size_t)(n * 128 + 2 * cp) * 784 + q];
    const float4 v1 = ((const float4*)in)[(size_t)(n * 128 + 2 * cp + 1) * 784 + q];
    uint4 o;
    o.x = pack_h2(v0.x, v1.x);
    o.y = pack_h2(v0.y, v1.y);
    o.z = pack_h2(v0.z, v1.z);
    o.w = pack_h2(v0.w, v1.w);
    ((uint4*)g_in_h)[(size_t)ncp * 784 + q] = o;
}

// ---- prep: weights -> fp16x2 fragment order ----
// word(idx): block = idx>>10 -> (s, nq); w = idx&1023 -> ks,fp,lane,j
__global__ void prep_w_kernel(const float* __restrict__ wsrc) {
    const int idx   = blockIdx.x * blockDim.x + threadIdx.x;  // [0, 147456)
    const int block = idx >> 10;
    const int s     = block >> 2;
    const int nq    = block & 3;
    const int w     = idx & 1023;
    const int ks    = w >> 9;
    const int fp    = (w >> 7) & 3;
    const int lane  = (w >> 2) & 31;
    const int j     = w & 3;
    const int grp   = lane >> 2;
    const int tig   = lane & 3;
    const int r     = j & 1;
    const int fh    = j >> 1;
    const int oc    = nq * 64 + (fp * 2 + fh) * 8 + grp;
    const int cblk  = s / 9;
    const int rs    = s - 9 * cblk;
    const int c0    = cblk * 32 + ks * 16 + r * 8 + tig * 2;
    const float w0 = wsrc[(size_t)oc * K_TOTAL + c0 * 9 + rs];
    const float w1 = wsrc[(size_t)oc * K_TOTAL + (c0 + 1) * 9 + rs];
    g_w_h[idx] = pack_h2(w0, w1);
}

__global__ void __launch_bounds__(THREADS, 4)
conv2d_mma_kernel(const float* __restrict__ bias, float* __restrict__ out)
{
    extern __shared__ char smem_raw[];
    const uint32_t sbase = smem_u32(smem_raw);

    const int tid     = threadIdx.x;
    const int lane    = tid & 31;
    const int wid     = tid >> 5;
    const int m_base  = blockIdx.x * BM;
    const int nq      = blockIdx.y;            // oc quarter 0..3
    const int oc_base = nq * BN;

    // ---- raw A loader: thread -> (ch-pair row cpl=tid>>4, 4-u32 chunks) ----
    const int cpl = tid >> 4;                  // 0..15
    const int gl0 = (tid & 15) * 4;

    auto load_A = [&](int cblk) {
        const uint32_t dbase = sbase + A_OFF(cblk & 1) + (uint32_t)(cpl * ASTRIDE * 4);
        const uint32_t* plane = g_in_h + (size_t)(cblk * 16 + cpl) * HW;
        #pragma unroll
        for (int j = 0; j < 4; j++) {
            const int gl = gl0 + 64 * j;
            if (gl >= ASTRIDE) break;          // gl==248,252 skipped
            const int g0 = m_base - 60 + gl;
            const uint32_t dst = dbase + (uint32_t)(gl * 4);
            bool fast = (g0 >= 0) && (g0 + 3 < M_TOTAL);
            int n = 0, rem = 0;
            if (fast) {
                n = g0 / HW; rem = g0 - n * HW;
                fast = (rem <= HW - 4);
            }
            if (fast) {
                cp16(dst, plane + (size_t)n * (64 * HW) + rem);
            } else {
                #pragma unroll
                for (int e = 0; e < 4; e++) {
                    const int g = g0 + e;
                    const uint32_t* src = g_in_h;
                    uint32_t sz = 0;
                    if (g >= 0 && g < M_TOTAL) {
                        const int nn = g / HW;
                        src = plane + (size_t)nn * (64 * HW) + (g - nn * HW);
                        sz = 4;
                    }
                    cp4_zfill(dst + 4 * e, src, sz);
                }
            }
        }
    };

    auto load_B = [&](int s) {
        const uint32_t dst = sbase + B_OFF(s % 3) + (uint32_t)(tid * 16);
        cp16(dst, g_w_h + (size_t)(s * 4 + nq) * 1024 + tid * 4);
    };

    // ---- compute mapping: 4(M) x 2(N) warps, warp tile 32x32 ----
    const int wm  = wid & 3;
    const int wn  = wid >> 2;
    const int grp = lane >> 2;
    const int tig = lane & 3;

    const int mrow0 = wm * 32 + grp;
    int hh[4], ww[4];
    #pragma unroll
    for (int i = 0; i < 4; i++) {
        const int m  = m_base + mrow0 + 8 * i;
        const int nn = m / HW;
        const int hw = m - nn * HW;
        hh[i] = hw / W_DIM;
        ww[i] = hw - hh[i] * W_DIM;
    }

    float acc[2][4][4];
    #pragma unroll
    for (int mi = 0; mi < 2; mi++)
        #pragma unroll
        for (int ni = 0; ni < 4; ni++)
            #pragma unroll
            for (int q = 0; q < 4; q++) acc[mi][ni][q] = 0.0f;

    // ---- prologue: 3 commit groups in flight ----
    load_A(0); load_B(0);
    asm volatile("cp.async.commit_group;" ::: "memory");
    load_A(1); load_B(1);
    asm volatile("cp.async.commit_group;" ::: "memory");
    load_B(2);
    asm volatile("cp.async.commit_group;" ::: "memory");

    int tap = 0, cblk = 0, dh = -1, dw = -1;
    for (int s = 0; s < NSTAGES; s++) {
        asm volatile("cp.async.wait_group 2;" ::: "memory");
        __syncthreads();

        const uint32_t Ab = sbase + A_OFF(cblk & 1);
        const uint32_t Bb = sbase + B_OFF(s % 3);

        const int offp = dh * W_DIM + dw + 60;
        // abase folds pixel base + tig channel-pair offset
        const uint32_t abase = Ab + (uint32_t)((mrow0 + offp) * 4) + (uint32_t)(tig * 992);
        const uint32_t baddr = Bb + (uint32_t)(wn * 1024 + lane * 16);
        bool val[4];
        #pragma unroll
        for (int i = 0; i < 4; i++)
            val[i] = ((unsigned)(hh[i] + dh) < (unsigned)H_DIM) &&
                     ((unsigned)(ww[i] + dw) < (unsigned)W_DIM);

        #pragma unroll
        for (int ks = 0; ks < 2; ks++) {
            const uint32_t kso = (uint32_t)(ks * 7936);     // 8 ch-pairs * 992
            uint32_t a[2][4];
            #pragma unroll
            for (int mi = 0; mi < 2; mi++) {
                const uint32_t p = abase + kso + (uint32_t)(mi * 64);
                const uint32_t v0 = lds32(p);
                const uint32_t v1 = lds32(p + 32);
                const uint32_t v2 = lds32(p + 3968);
                const uint32_t v3 = lds32(p + 3968 + 32);
                a[mi][0] = val[2 * mi]     ? v0 : 0u;
                a[mi][1] = val[2 * mi + 1] ? v1 : 0u;
                a[mi][2] = val[2 * mi]     ? v2 : 0u;
                a[mi][3] = val[2 * mi + 1] ? v3 : 0u;
            }
            uint32_t bb[2][4];
            #pragma unroll
            for (int q = 0; q < 2; q++)
                lds128(bb[q], baddr + (uint32_t)(ks * 2048 + q * 512));
            #pragma unroll
            for (int q = 0; q < 2; q++)
                #pragma unroll
                for (int sub = 0; sub < 2; sub++) {
                    const int ni = q * 2 + sub;
                    #pragma unroll
                    for (int mi = 0; mi < 2; mi++)
                        mma_f16(acc[mi][ni], a[mi],
                                bb[q][sub * 2], bb[q][sub * 2 + 1]);
                }
        }
        __syncthreads();

        if (s + 3 < NSTAGES) load_B(s + 3);
        if (tap == 0 && cblk < 3) load_A(cblk + 1);
        asm volatile("cp.async.commit_group;" ::: "memory");

        if (++tap == 9) { tap = 0; cblk++; dh = -1; dw = -1; }
        else { if (++dw == 2) { dw = -1; dh++; } }
    }

    // ---- epilogue: +bias, scatter to NCHW ----
    #pragma unroll
    for (int mi = 0; mi < 2; mi++) {
        #pragma unroll
        for (int hf = 0; hf < 2; hf++) {
            const int m   = m_base + mrow0 + mi * 16 + 8 * hf;
            const int nn  = m / HW;
            const int phw = m - nn * HW;
            float* op = out + (size_t)nn * OC_DIM * HW + phw;
            #pragma unroll
            for (int ni = 0; ni < 4; ni++) {
                const int oc = oc_base + wn * 32 + ni * 8 + 2 * tig;
                const float b0 = __ldg(bias + oc);
                const float b1 = __ldg(bias + oc + 1);
                op[(size_t)oc * HW]       = acc[mi][ni][2 * hf + 0] + b0;
                op[(size_t)(oc + 1) * HW] = acc[mi][ni][2 * hf + 1] + b1;
            }
        }
    }
}

extern "C" void kernel_launch(void* const* d_in, const int* in_sizes, int n_in,
                              void* d_out, int out_size)
{
    const float* in   = (const float*)d_in[0];
    const float* wgt  = (const float*)d_in[1];
    const float* bias = (const float*)d_in[2];
    float* out        = (float*)d_out;

    prep_in_kernel<<<(N_IMG * 64 * 784) / 256, 256>>>(in);
    prep_w_kernel<<<(OC_DIM * K_TOTAL / 2) / 256, 256>>>(wgt);

    cudaFuncSetAttribute(conv2d_mma_kernel,
                         cudaFuncAttributeMaxDynamicSharedMemorySize, SMEM_TOTAL);
    dim3 grid(M_TOTAL / BM, OC_DIM / BN, 1);   // 784 x 4
    conv2d_mma_kernel<<<grid, THREADS, SMEM_TOTAL>>>(bias, out);
}

// round 10
// speedup vs baseline: 2.9852x; 1.3900x over previous
#include <cuda_runtime.h>
#include <cuda_fp16.h>
#include <cstdint>

// Conv2d 3x3 s1 p1 NCHW fp32: N=32,C=128,H=W=56,OC=256.
// Implicit GEMM mma.sync.m16n8k16 FP16 (fp32 accum). K' = cblk*288 + tap*32 + c.
// R10: R9 (pixel-major raw A tile + ldmatrix.x4, warp tile 32x64) with the
// halo zero-slot widened to 64B (R9 read zaddr+32 past a 16B slot -> NaN).

#define N_IMG   32
#define C_IN    128
#define H_DIM   56
#define W_DIM   56
#define OC_DIM  256
#define HW      3136
#define CHW     (C_IN * HW)
#define K_TOTAL 1152
#define M_TOTAL 100352

#define BM 128
#define BN 128
#define THREADS 256
#define NSTAGES 36                       // 4 cblk * 9 taps

#define NPIX 248                         // 128 m + halo
#define ROWB 80                          // bytes per pixel row (64 data + 16 pad)
#define ABUF_BYTES (NPIX * ROWB)         // 19840
#define B_STAGE_BYTES 8192               // 128 oc x 32 k x 2B
#define A_OFF(i) ((i) * ABUF_BYTES)
#define B_OFF(j) (2 * ABUF_BYTES + (j) * B_STAGE_BYTES)
#define OFF_ZERO (2 * ABUF_BYTES + 3 * B_STAGE_BYTES)     // 64256
#define SMEM_TOTAL (OFF_ZERO + 64)       // 64320 (64B zero slot)

__device__ __align__(16) uint32_t g_in_h2[(size_t)M_TOTAL * 64]; // [pix][cp] fp16x2
__device__ __align__(16) uint32_t g_w_h[OC_DIM * K_TOTAL / 2];   // frag-order fp16x2

__device__ __forceinline__ uint32_t smem_u32(const void* p) {
    uint32_t a;
    asm("{ .reg .u64 t; cvta.to.shared.u64 t, %1; cvt.u32.u64 %0, t; }" : "=r"(a) : "l"(p));
    return a;
}
__device__ __forceinline__ uint32_t pack_h2(float lo, float hi) {
    __half2 h = __halves2half2(__float2half_rn(lo), __float2half_rn(hi));
    return *reinterpret_cast<uint32_t*>(&h);
}
__device__ __forceinline__ void cp16_zfill(uint32_t dst, const void* src, uint32_t sz) {
    asm volatile("cp.async.cg.shared.global [%0], [%1], 16, %2;"
                 :: "r"(dst), "l"(src), "r"(sz) : "memory");
}
__device__ __forceinline__ void cp16(uint32_t dst, const void* src) {
    asm volatile("cp.async.cg.shared.global [%0], [%1], 16;"
                 :: "r"(dst), "l"(src) : "memory");
}
__device__ __forceinline__ void lds128(uint32_t* r, uint32_t addr) {
    asm volatile("ld.shared.v4.u32 {%0,%1,%2,%3}, [%4];"
                 : "=r"(r[0]), "=r"(r[1]), "=r"(r[2]), "=r"(r[3]) : "r"(addr));
}
__device__ __forceinline__ void ldmx4(uint32_t* r, uint32_t addr) {
    asm volatile("ldmatrix.sync.aligned.m8n8.x4.shared.b16 {%0,%1,%2,%3}, [%4];"
                 : "=r"(r[0]), "=r"(r[1]), "=r"(r[2]), "=r"(r[3]) : "r"(addr));
}
__device__ __forceinline__ void mma_f16(float* c, const uint32_t* a,
                                        uint32_t b0, uint32_t b1) {
    asm volatile(
        "mma.sync.aligned.m16n8k16.row.col.f32.f16.f16.f32 "
        "{%0,%1,%2,%3}, {%4,%5,%6,%7}, {%8,%9}, {%0,%1,%2,%3};"
        : "+f"(c[0]), "+f"(c[1]), "+f"(c[2]), "+f"(c[3])
        : "r"(a[0]), "r"(a[1]), "r"(a[2]), "r"(a[3]), "r"(b0), "r"(b1));
}

// ---- prep: input NCHW fp32 -> [pixel][cp] fp16x2 (tiled smem transpose) ----
__global__ void prep_in_kernel(const float* __restrict__ in) {
    __shared__ float sm[128][33];
    const int tid = threadIdx.x;
    const int n   = blockIdx.x / 98;
    const int hw0 = (blockIdx.x - n * 98) * 32;

    const int c    = tid >> 1;
    const int part = tid & 1;
    const float4* s4 = (const float4*)(in + (size_t)n * CHW + (size_t)c * HW
                                       + hw0 + part * 16);
    #pragma unroll
    for (int e = 0; e < 4; e++) {
        const float4 v = s4[e];
        sm[c][part * 16 + e * 4 + 0] = v.x;
        sm[c][part * 16 + e * 4 + 1] = v.y;
        sm[c][part * 16 + e * 4 + 2] = v.z;
        sm[c][part * 16 + e * 4 + 3] = v.w;
    }
    __syncthreads();

    const int hw_l = tid >> 3;
    const int cq   = tid & 7;
    uint32_t ow[8];
    #pragma unroll
    for (int e = 0; e < 8; e++) {
        const int cp = cq * 8 + e;
        ow[e] = pack_h2(sm[2 * cp][hw_l], sm[2 * cp + 1][hw_l]);
    }
    uint4* dst = (uint4*)(g_in_h2 + (size_t)(n * HW + hw0 + hw_l) * 64 + cq * 8);
    dst[0] = make_uint4(ow[0], ow[1], ow[2], ow[3]);
    dst[1] = make_uint4(ow[4], ow[5], ow[6], ow[7]);
}

// ---- prep: weights -> fp16x2 fragment order ----
// g_w_h layout: [s(36)][half(2)][ks(2)][wn(2)][q(4)][lane(32)][j(4)]
__global__ void prep_w_kernel(const float* __restrict__ wsrc) {
    const int idx  = blockIdx.x * blockDim.x + threadIdx.x;   // [0, 147456)
    const int s    = idx >> 12;
    const int w2   = idx & 4095;
    const int half = w2 >> 11;
    const int w    = w2 & 2047;
    const int ks   = w >> 10;
    const int wn   = (w >> 9) & 1;
    const int q    = (w >> 7) & 3;
    const int lane = (w >> 2) & 31;
    const int j    = w & 3;
    const int grp  = lane >> 2;
    const int tig  = lane & 3;
    const int oc   = half * 128 + wn * 64 + (2 * q + (j >> 1)) * 8 + grp;
    const int c0   = ks * 16 + (j & 1) * 8 + tig * 2;
    const int cblk = s / 9;
    const int rs   = s - 9 * cblk;
    const int ch   = cblk * 32 + c0;
    const float w0 = wsrc[(size_t)oc * K_TOTAL + ch * 9 + rs];
    const float w1 = wsrc[(size_t)oc * K_TOTAL + (ch + 1) * 9 + rs];
    g_w_h[idx] = pack_h2(w0, w1);
}

__global__ void __launch_bounds__(THREADS, 2)
conv2d_mma_kernel(const float* __restrict__ bias, float* __restrict__ out)
{
    extern __shared__ char smem_raw[];
    const uint32_t sbase = smem_u32(smem_raw);
    const uint32_t zaddr = sbase + OFF_ZERO;

    const int tid     = threadIdx.x;
    const int lane    = tid & 31;
    const int wid     = tid >> 5;
    const int m_base  = blockIdx.x * BM;
    const int nh      = blockIdx.y;            // oc half
    const int oc_base = nh * BN;

    if (tid < 16) ((uint32_t*)(smem_raw + OFF_ZERO))[tid] = 0u;

    // ---- A loader: 992 16B chunks (248 pixels x 4) ----
    auto load_A = [&](int cblk) {
        const uint32_t dbase = sbase + A_OFF(cblk & 1);
        #pragma unroll
        for (int j = 0; j < 4; j++) {
            const int ch_i = tid + 256 * j;
            if (ch_i >= NPIX * 4) break;
            const int pix = ch_i >> 2;
            const int t   = ch_i & 3;
            const int g   = m_base - 60 + pix;
            const bool ok = (g >= 0) && (g < M_TOTAL);
            const size_t gc = ok ? (size_t)g : 0;
            cp16_zfill(dbase + (uint32_t)(pix * ROWB + t * 16),
                       g_in_h2 + gc * 64 + cblk * 16 + t * 4,
                       ok ? 16u : 0u);
        }
    };
    auto load_B = [&](int s) {
        const uint32_t dst = sbase + B_OFF(s % 3) + (uint32_t)(tid * 16);
        const uint32_t* src = g_w_h + (size_t)s * 4096 + nh * 2048 + tid * 4;
        cp16(dst, src);
        cp16(dst + 4096, src + 1024);
    };

    // ---- compute mapping: 4(M) x 2(N) warps, warp tile 32x64 ----
    const int wm  = wid & 3;
    const int wn  = wid >> 2;
    const int grp = lane >> 2;
    const int tig = lane & 3;
    const int l15 = lane & 15;
    const int khalf = lane >> 4;

    // per-lane ldmatrix row pixels (mi = 0,1)
    int pixloc[2], hh[2], ww[2];
    #pragma unroll
    for (int mi = 0; mi < 2; mi++) {
        const int mrow = wm * 32 + mi * 16 + l15;
        pixloc[mi] = mrow + 60;
        const int m  = m_base + mrow;
        const int nn = m / HW;
        const int hw = m - nn * HW;
        hh[mi] = hw / W_DIM;
        ww[mi] = hw - hh[mi] * W_DIM;
    }

    float acc[2][8][4];
    #pragma unroll
    for (int mi = 0; mi < 2; mi++)
        #pragma unroll
        for (int ni = 0; ni < 8; ni++)
            #pragma unroll
            for (int q = 0; q < 4; q++) acc[mi][ni][q] = 0.0f;

    load_A(0); load_B(0);
    asm volatile("cp.async.commit_group;" ::: "memory");
    load_A(1); load_B(1);
    asm volatile("cp.async.commit_group;" ::: "memory");
    load_B(2);
    asm volatile("cp.async.commit_group;" ::: "memory");

    int tap = 0, cblk = 0, dh = -1, dw = -1;
    for (int s = 0; s < NSTAGES; s++) {
        asm volatile("cp.async.wait_group 2;" ::: "memory");
        __syncthreads();

        const uint32_t Ab = sbase + A_OFF(cblk & 1);
        const uint32_t Bb = sbase + B_OFF(s % 3);
        const int shift = dh * W_DIM + dw;

        // per-lane A row addresses (zero-slot redirect outside image;
        // redirected reads hit [zaddr, zaddr+48] — slot is 64B)
        uint32_t ra[2];
        #pragma unroll
        for (int mi = 0; mi < 2; mi++) {
            const bool ok = ((unsigned)(hh[mi] + dh) < (unsigned)H_DIM) &&
                            ((unsigned)(ww[mi] + dw) < (unsigned)W_DIM);
            ra[mi] = ok ? (Ab + (uint32_t)((pixloc[mi] + shift) * ROWB + khalf * 16))
                        : zaddr;
        }

        const uint32_t bb_base = Bb + (uint32_t)(wn * 2048 + lane * 16);
        #pragma unroll
        for (int ks = 0; ks < 2; ks++) {
            uint32_t a[2][4];
            ldmx4(a[0], ra[0] + ks * 32);
            ldmx4(a[1], ra[1] + ks * 32);
            uint32_t bb[4][4];
            #pragma unroll
            for (int q = 0; q < 4; q++)
                lds128(bb[q], bb_base + (uint32_t)(ks * 4096 + q * 512));
            #pragma unroll
            for (int q = 0; q < 4; q++)
                #pragma unroll
                for (int sub = 0; sub < 2; sub++) {
                    const int ni = q * 2 + sub;
                    #pragma unroll
                    for (int mi = 0; mi < 2; mi++)
                        mma_f16(acc[mi][ni], a[mi],
                                bb[q][sub * 2], bb[q][sub * 2 + 1]);
                }
        }
        __syncthreads();

        if (s + 3 < NSTAGES) load_B(s + 3);
        if (tap == 0 && cblk < 3) load_A(cblk + 1);
        asm volatile("cp.async.commit_group;" ::: "memory");

        if (++tap == 9) { tap = 0; cblk++; dh = -1; dw = -1; }
        else { if (++dw == 2) { dw = -1; dh++; } }
    }

    // ---- epilogue: +bias, scatter to NCHW ----
    #pragma unroll
    for (int mi = 0; mi < 2; mi++) {
        #pragma unroll
        for (int hf = 0; hf < 2; hf++) {
            const int m   = m_base + wm * 32 + mi * 16 + grp + 8 * hf;
            const int nn  = m / HW;
            const int phw = m - nn * HW;
            float* op = out + (size_t)nn * OC_DIM * HW + phw;
            #pragma unroll
            for (int ni = 0; ni < 8; ni++) {
                const int oc = oc_base + wn * 64 + ni * 8 + 2 * tig;
                const float b0 = __ldg(bias + oc);
                const float b1 = __ldg(bias + oc + 1);
                op[(size_t)oc * HW]       = acc[mi][ni][2 * hf + 0] + b0;
                op[(size_t)(oc + 1) * HW] = acc[mi][ni][2 * hf + 1] + b1;
            }
        }
    }
}

extern "C" void kernel_launch(void* const* d_in, const int* in_sizes, int n_in,
                              void* d_out, int out_size)
{
    const float* in   = (const float*)d_in[0];
    const float* wgt  = (const float*)d_in[1];
    const float* bias = (const float*)d_in[2];
    float* out        = (float*)d_out;

    prep_in_kernel<<<32 * 98, 256>>>(in);
    prep_w_kernel<<<(OC_DIM * K_TOTAL / 2) / 256, 256>>>(wgt);

    cudaFuncSetAttribute(conv2d_mma_kernel,
                         cudaFuncAttributeMaxDynamicSharedMemorySize, SMEM_TOTAL);
    dim3 grid(M_TOTAL / BM, OC_DIM / BN, 1);   // 784 x 2
    conv2d_mma_kernel<<<grid, THREADS, SMEM_TOTAL>>>(bias, out);
}